// round 14
// baseline (speedup 1.0000x reference)
#include <cuda_runtime.h>

#define BB       4096
#define VOCABN   50000
#define FF       64
#define K_PAD    50176       // 14 * 3584 = 784 * 64, B zero-padded beyond 50000
#define K_SPLITS 14
#define K_PER    3584        // 28 * 128
#define ITERS    28
#define TILE_K   128
#define M_TILES  32
#define NB       64          // V cols only; c handled via dp4a
#define BROW8    144         // int8 smem row stride (128 data + 16 pad)
#define LIMB_B   (NB * BROW8)   // 9216 bytes per limb per stage
#define SC_OFF   36864          // sC after sB (2*2*LIMB_B = 36864)
#define A_OFF    37376          // A ring after sC (512B, 16B aligned)
#define A_SLOT   16384          // 128 threads * 8 chunks * 16B
#define SMEM_MAIN (A_OFF + 2 * A_SLOT)   // 70144 bytes -> 3 CTAs/SM

// ---- device-global scratch (zero-initialized at load; invariant restored by fm_fin) ----
__device__ __align__(16) signed char g_Bh8[NB * K_PAD];
__device__ __align__(16) signed char g_Bl8[NB * K_PAD];
__device__ __align__(16) signed char g_ch8[K_PAD];
__device__ __align__(16) signed char g_cl8[K_PAD];
__device__ float g_xv[BB * FF];
__device__ float g_xc[BB];
__device__ int   g_maxb[2];      // [0] = max|V|, [1] = max|c|

__device__ __forceinline__ unsigned s2u(const void* p) {
    return (unsigned)__cvta_generic_to_shared(p);
}
__device__ __forceinline__ void cp16(void* dst, const void* src) {
    asm volatile("cp.async.cg.shared.global [%0], [%1], 16;"
                 :: "r"(s2u(dst)), "l"(src));
}
__device__ __forceinline__ void ldsm4(unsigned* r, unsigned addr) {
    asm volatile("ldmatrix.sync.aligned.m8n8.x4.shared.b16 {%0,%1,%2,%3}, [%4];"
                 : "=r"(r[0]), "=r"(r[1]), "=r"(r[2]), "=r"(r[3]) : "r"(addr));
}
__device__ __forceinline__ void mma_s8(int* d, const unsigned* a, unsigned b0, unsigned b1) {
    asm volatile(
        "mma.sync.aligned.m16n8k32.row.col.s32.s8.s8.s32 "
        "{%0,%1,%2,%3}, {%4,%5,%6,%7}, {%8,%9}, {%0,%1,%2,%3};"
        : "+r"(d[0]), "+r"(d[1]), "+r"(d[2]), "+r"(d[3])
        : "r"(a[0]), "r"(a[1]), "r"(a[2]), "r"(a[3]), "r"(b0), "r"(b1));
}

// ---------------- pass 1: global max|V| and max|c| ----------------
__global__ void fm_scale1(const float* __restrict__ V, const float* __restrict__ bias) {
    __shared__ int sm2[2];
    int tid = threadIdx.x, lane = tid & 31;
    if (tid < 2) sm2[tid] = 0;
    __syncthreads();
    int r = blockIdx.x * 256 + tid;
    float vmax = 0.f, cabs = 0.f;
    if (r < VOCABN) {
        const float4* vr = (const float4*)(V + (size_t)r * 64);
        float ss = 0.f;
        #pragma unroll
        for (int j = 0; j < 16; j++) {
            float4 v = vr[j];
            ss += v.x*v.x + v.y*v.y + v.z*v.z + v.w*v.w;
            vmax = fmaxf(vmax, fmaxf(fmaxf(fabsf(v.x), fabsf(v.y)),
                                     fmaxf(fabsf(v.z), fabsf(v.w))));
        }
        cabs = fabsf(bias[r] - 0.5f * ss);
    }
    #pragma unroll
    for (int off = 16; off > 0; off >>= 1) {
        vmax = fmaxf(vmax, __shfl_xor_sync(0xFFFFFFFFu, vmax, off));
        cabs = fmaxf(cabs, __shfl_xor_sync(0xFFFFFFFFu, cabs, off));
    }
    if (lane == 0) {
        atomicMax(&sm2[0], __float_as_int(vmax));
        atomicMax(&sm2[1], __float_as_int(cabs));
    }
    __syncthreads();
    if (tid < 2) atomicMax(&g_maxb[tid], sm2[tid]);
}

__device__ __forceinline__ void quant2(float v, float s, signed char& h8, signed char& l8) {
    float q = v * s;
    float h = rintf(q);
    float l = rintf((q - h) * 256.f);
    if (l > 127.f) l = 127.f;
    h8 = (signed char)(int)h;
    l8 = (signed char)(int)l;
}

// ---------------- pass 2: quantize V cols + c; conflict-free transposed smem ----------------
__global__ void fm_prep(const float* __restrict__ V, const float* __restrict__ bias) {
    __shared__ float smT[64][68];
    int i0 = blockIdx.x * 64;
    int tid = threadIdx.x;

    float mV = __int_as_float(g_maxb[0]);
    float sV = (mV > 0.f) ? 127.f / mV : 1.f;
    float mC = __int_as_float(g_maxb[1]);
    float sC = (mC > 0.f) ? 127.f / mC : 1.f;

    #pragma unroll
    for (int pass = 0; pass < 4; pass++) {
        int idx = pass * 256 + tid;
        int i  = idx & 63;
        int f4 = (idx >> 6) * 4;
        int gi = i0 + i;
        float4 v = (gi < VOCABN)
                 ? *(const float4*)(V + (size_t)gi * 64 + f4)
                 : make_float4(0.f, 0.f, 0.f, 0.f);
        smT[f4 + 0][i] = v.x;
        smT[f4 + 1][i] = v.y;
        smT[f4 + 2][i] = v.z;
        smT[f4 + 3][i] = v.w;
    }
    __syncthreads();

    if (tid < 64) {
        float ssum = 0.f;
        #pragma unroll
        for (int f = 0; f < 64; f++) { float v = smT[f][tid]; ssum += v * v; }
        int gi = i0 + tid;
        float cv = (gi < VOCABN) ? (bias[gi] - 0.5f * ssum) : 0.f;
        signed char h8, l8;
        quant2(cv, sC, h8, l8);
        g_ch8[i0 + tid] = h8;
        g_cl8[i0 + tid] = l8;
    }

    #pragma unroll
    for (int pass = 0; pass < 4; pass++) {
        int idx = pass * 256 + tid;
        int f  = idx >> 4;
        int i4 = (idx & 15) * 4;
        float4 v = *(const float4*)&smT[f][i4];
        char4 h4, l4;
        quant2(v.x, sV, (signed char&)h4.x, (signed char&)l4.x);
        quant2(v.y, sV, (signed char&)h4.y, (signed char&)l4.y);
        quant2(v.z, sV, (signed char&)h4.z, (signed char&)l4.z);
        quant2(v.w, sV, (signed char&)h4.w, (signed char&)l4.w);
        *(char4*)&g_Bh8[(size_t)f * K_PAD + i0 + i4] = h4;
        *(char4*)&g_Bl8[(size_t)f * K_PAD + i0 + i4] = l4;
    }
}

// ---------------- main: split-K s8 GEMM + dp4a linear term; 3 CTAs/SM, 2-slot A ring ----------------
__global__ void __launch_bounds__(128, 3) fm_main(const int* __restrict__ x) {
    extern __shared__ __align__(16) char dsm[];
    const unsigned sbase = s2u(dsm);

    const int tid  = threadIdx.x;
    const int w    = tid >> 5;
    const int lane = tid & 31;
    const int gid  = lane >> 2;
    const int t4   = (lane & 3) * 4;
    const int t2   = (lane & 3) * 2;
    const int mt   = blockIdx.x & (M_TILES - 1);
    const int ks   = blockIdx.x >> 5;
    const int m0   = mt * 128;
    const int k0   = ks * K_PER;

    const int* xr[4];
    bool nl[4];
    #pragma unroll
    for (int j = 0; j < 4; j++) {
        int r = m0 + w * 32 + j * 8 + gid;
        xr[j] = x + (size_t)r * VOCABN;
        nl[j] = (r != BB - 1);
    }

    int accH[8][2][4], accL[8][2][4];
    #pragma unroll
    for (int n = 0; n < 8; n++)
        #pragma unroll
        for (int m = 0; m < 2; m++)
            #pragma unroll
            for (int i = 0; i < 4; i++) { accH[n][m][i] = 0; accL[n][m][i] = 0; }
    int cH[4] = {0, 0, 0, 0}, cL[4] = {0, 0, 0, 0};

    auto stageB = [&](int st, int k) {
        #pragma unroll
        for (int j = 0; j < 8; j++) {
            int c = tid + j * 128;
            int limb = (c >= 512) ? 1 : 0;
            int cc = c - limb * 512;
            int n = cc >> 3, ch = cc & 7;
            const signed char* g = limb ? g_Bl8 : g_Bh8;
            cp16(dsm + st * (2 * LIMB_B) + limb * LIMB_B + n * BROW8 + ch * 16,
                 g + (size_t)n * K_PAD + k + ch * 16);
        }
        if (tid < 16) {
            int limb = tid >> 3, ch = tid & 7;
            const signed char* g = limb ? g_cl8 : g_ch8;
            cp16(dsm + SC_OFF + st * 256 + limb * 128 + ch * 16, g + k + ch * 16);
        }
        asm volatile("cp.async.commit_group;");
    };

    // A batch g -> ring slot g&1 (8x16B per thread, self-consumed)
    auto cpA = [&](int g) {
        char* base = dsm + A_OFF + (g & 1) * A_SLOT + tid * 16;
        int cb = k0 + g * 32;
        #pragma unroll
        for (int mf = 0; mf < 2; mf++)
            #pragma unroll
            for (int q = 0; q < 4; q++) {
                int i = mf * 4 + q;
                const int* p = xr[mf * 2 + (q & 1)];
                int c = cb + (q >> 1) * 16 + t4;
                char* dst = base + i * 2048;
                if (nl[mf * 2 + (q & 1)] | (c < VOCABN)) cp16(dst, p + c);
                else *(int4*)dst = make_int4(0, 0, 0, 0);
            }
        asm volatile("cp.async.commit_group;");
    };

    unsigned pa[8];
    auto consumeA = [&](int g) {
        const char* base = dsm + A_OFF + (g & 1) * A_SLOT + tid * 16;
        #pragma unroll
        for (int i = 0; i < 8; i++) {
            int4 v = *(const int4*)(base + i * 2048);
            pa[i] = (unsigned)v.x | ((unsigned)v.y << 8)
                  | ((unsigned)v.z << 16) | ((unsigned)v.w << 24);
        }
    };

    const unsigned offX4 = (unsigned)((lane & 15) * BROW8 + (lane >> 4) * 16);

    auto doLimb = [&](unsigned lb, int (&acc)[8][2][4]) {
        #pragma unroll
        for (int j = 0; j < 4; j++) {
            unsigned bm[4];
            ldsm4(bm, lb + (unsigned)j * (16 * BROW8) + offX4);
            #pragma unroll
            for (int mf = 0; mf < 2; mf++) {
                mma_s8(acc[2 * j][mf],     pa + mf * 4, bm[0], bm[2]);
                mma_s8(acc[2 * j + 1][mf], pa + mf * 4, bm[1], bm[3]);
            }
        }
    };

    // prologue: B stage 0 + A batches 0,1 (first s-step wait guarantees B0+A0)
    stageB(0, k0);
    cpA(0); cpA(1);

    for (int it = 0; it < ITERS; it++) {
        const int p = it & 1;
        __syncthreads();
        if (it + 1 < ITERS) stageB(p ^ 1, k0 + (it + 1) * TILE_K);

        int wc[4][4];
        #pragma unroll
        for (int s = 0; s < 4; s++) {
            wc[s][0] = *(const int*)(dsm + SC_OFF + p * 256 + s * 32 + t4);
            wc[s][1] = *(const int*)(dsm + SC_OFF + p * 256 + s * 32 + 16 + t4);
            wc[s][2] = *(const int*)(dsm + SC_OFF + p * 256 + 128 + s * 32 + t4);
            wc[s][3] = *(const int*)(dsm + SC_OFF + p * 256 + 128 + s * 32 + 16 + t4);
        }

        const unsigned stb = sbase + (unsigned)p * (2 * LIMB_B);
        #pragma unroll
        for (int s = 0; s < 4; s++) {
            const int g = it * 4 + s;
            // leave only the single most recent commit pending -> A(g) complete
            asm volatile("cp.async.wait_group 1;");
            consumeA(g);
            cpA(g + 2);                         // refill slot just consumed
            {
                cH[0] = __dp4a((int)pa[0], wc[s][0], cH[0]);
                cH[1] = __dp4a((int)pa[1], wc[s][0], cH[1]);
                cH[0] = __dp4a((int)pa[2], wc[s][1], cH[0]);
                cH[1] = __dp4a((int)pa[3], wc[s][1], cH[1]);
                cH[2] = __dp4a((int)pa[4], wc[s][0], cH[2]);
                cH[3] = __dp4a((int)pa[5], wc[s][0], cH[3]);
                cH[2] = __dp4a((int)pa[6], wc[s][1], cH[2]);
                cH[3] = __dp4a((int)pa[7], wc[s][1], cH[3]);
                cL[0] = __dp4a((int)pa[0], wc[s][2], cL[0]);
                cL[1] = __dp4a((int)pa[1], wc[s][2], cL[1]);
                cL[0] = __dp4a((int)pa[2], wc[s][3], cL[0]);
                cL[1] = __dp4a((int)pa[3], wc[s][3], cL[1]);
                cL[2] = __dp4a((int)pa[4], wc[s][2], cL[2]);
                cL[3] = __dp4a((int)pa[5], wc[s][2], cL[3]);
                cL[2] = __dp4a((int)pa[6], wc[s][3], cL[2]);
                cL[3] = __dp4a((int)pa[7], wc[s][3], cL[3]);
            }
            doLimb(stb + (unsigned)s * 32, accH);
            doLimb(stb + LIMB_B + (unsigned)s * 32, accL);
        }
    }

    // ---- epilogue: dequant + split-K accumulate ----
    float mV = __int_as_float(g_maxb[0]);
    float mC = __int_as_float(g_maxb[1]);
    const double invV = (mV > 0.f) ? (double)mV / 32512.0 : (1.0 / 256.0);
    const double invC = (mC > 0.f) ? (double)mC / 32512.0 : (1.0 / 256.0);

    #pragma unroll
    for (int mf = 0; mf < 2; mf++) {
        int rowA = m0 + w * 32 + mf * 16 + gid;
        #pragma unroll
        for (int nf = 0; nf < 8; nf++) {
            #pragma unroll
            for (int cc = 0; cc < 2; cc++) {
                int n = nf * 8 + t2 + cc;
                float v0 = (float)((double)(256LL * accH[nf][mf][cc]     + accL[nf][mf][cc])     * invV);
                float v1 = (float)((double)(256LL * accH[nf][mf][2 + cc] + accL[nf][mf][2 + cc]) * invV);
                atomicAdd(&g_xv[(size_t)rowA * FF + n],       v0);
                atomicAdd(&g_xv[(size_t)(rowA + 8) * FF + n], v1);
            }
        }
    }
    #pragma unroll
    for (int j = 0; j < 4; j++) {
        int h = cH[j], l = cL[j];
        h += __shfl_xor_sync(0xFFFFFFFFu, h, 1);
        h += __shfl_xor_sync(0xFFFFFFFFu, h, 2);
        l += __shfl_xor_sync(0xFFFFFFFFu, l, 1);
        l += __shfl_xor_sync(0xFFFFFFFFu, l, 2);
        if ((lane & 3) == 0) {
            int row = m0 + w * 32 + j * 8 + gid;
            atomicAdd(&g_xc[row],
                      (float)((double)(256LL * h + l) * invC));
        }
    }
}

// ---------------- finalize: out = g + xc + 0.5||xv||^2; re-zero scratch ----------------
__global__ void fm_fin(const float* __restrict__ gb, float* __restrict__ out) {
    int t = blockIdx.x * blockDim.x + threadIdx.x;
    int b = t >> 2, part = t & 3;
    float4* v = (float4*)&g_xv[(size_t)b * FF + part * 16];
    float ss = 0.f;
    #pragma unroll
    for (int i = 0; i < 4; i++) {
        float4 q = v[i];
        ss += q.x * q.x + q.y * q.y + q.z * q.z + q.w * q.w;
        v[i] = make_float4(0.f, 0.f, 0.f, 0.f);
    }
    ss += __shfl_xor_sync(0xFFFFFFFFu, ss, 1);
    ss += __shfl_xor_sync(0xFFFFFFFFu, ss, 2);
    if (part == 0) {
        out[b] = gb[0] + g_xc[b] + 0.5f * ss;
        g_xc[b] = 0.f;
    }
    if (t < 2) g_maxb[t] = 0;
}

extern "C" void kernel_launch(void* const* d_in, const int* in_sizes, int n_in,
                              void* d_out, int out_size) {
    const int*   x    = (const int*)d_in[0];
    const float* V    = (const float*)d_in[1];
    const float* bias = (const float*)d_in[2];
    const float* gb   = (const float*)d_in[3];
    float* out = (float*)d_out;
    (void)in_sizes; (void)n_in; (void)out_size;

    cudaFuncSetAttribute(fm_main, cudaFuncAttributeMaxDynamicSharedMemorySize, SMEM_MAIN);

    fm_scale1<<<196, 256>>>(V, bias);
    fm_prep<<<K_PAD / 64, 256>>>(V, bias);
    fm_main<<<M_TILES * K_SPLITS, 128, SMEM_MAIN>>>(x);
    fm_fin<<<64, 256>>>(gb, out);
}

// round 15
// speedup vs baseline: 1.5619x; 1.5619x over previous
#include <cuda_runtime.h>

#define BB       4096
#define VOCABN   50000
#define FF       64
#define K_PAD    50688       // 9 * 5632 = 792 * 64, B zero-padded beyond 50000
#define K_SPLITS 9
#define K_PER    5632        // 44 * 128
#define ITERS    44
#define TILE_K   128
#define M_TILES  32
#define NB       64          // V cols only; c handled via dp4a
#define BROW8    144         // int8 smem row stride (128 data + 16 pad)
#define LIMB_B   (NB * BROW8)   // 9216 bytes per limb per stage
#define SC_OFF   36864          // sC after sB (2*2*LIMB_B = 36864)
#define A_OFF    37376          // A ring after sC (512B, 16B aligned)
#define A_SLOT   16384          // 128 threads * 8 chunks * 16B
#define SMEM_MAIN (A_OFF + 4 * A_SLOT)   // 102912 bytes -> 2 CTAs/SM

// ---- device-global scratch (zero-initialized at load; invariant restored by fm_fin) ----
__device__ __align__(16) signed char g_Bh8[NB * K_PAD];
__device__ __align__(16) signed char g_Bl8[NB * K_PAD];
__device__ __align__(16) signed char g_ch8[K_PAD];
__device__ __align__(16) signed char g_cl8[K_PAD];
__device__ float g_xv[BB * FF];
__device__ float g_xc[BB];
__device__ int   g_maxb[2];      // [0] = max|V|, [1] = max|c|

__device__ __forceinline__ unsigned s2u(const void* p) {
    return (unsigned)__cvta_generic_to_shared(p);
}
__device__ __forceinline__ void cp16(void* dst, const void* src) {
    asm volatile("cp.async.cg.shared.global [%0], [%1], 16;"
                 :: "r"(s2u(dst)), "l"(src));
}
__device__ __forceinline__ void ldsm4(unsigned* r, unsigned addr) {
    asm volatile("ldmatrix.sync.aligned.m8n8.x4.shared.b16 {%0,%1,%2,%3}, [%4];"
                 : "=r"(r[0]), "=r"(r[1]), "=r"(r[2]), "=r"(r[3]) : "r"(addr));
}
__device__ __forceinline__ void mma_s8(int* d, const unsigned* a, unsigned b0, unsigned b1) {
    asm volatile(
        "mma.sync.aligned.m16n8k32.row.col.s32.s8.s8.s32 "
        "{%0,%1,%2,%3}, {%4,%5,%6,%7}, {%8,%9}, {%0,%1,%2,%3};"
        : "+r"(d[0]), "+r"(d[1]), "+r"(d[2]), "+r"(d[3])
        : "r"(a[0]), "r"(a[1]), "r"(a[2]), "r"(a[3]), "r"(b0), "r"(b1));
}

// ---------------- pass 1: global max|V| and max|c| ----------------
__global__ void fm_scale1(const float* __restrict__ V, const float* __restrict__ bias) {
    __shared__ int sm2[2];
    int tid = threadIdx.x, lane = tid & 31;
    if (tid < 2) sm2[tid] = 0;
    __syncthreads();
    int r = blockIdx.x * 256 + tid;
    float vmax = 0.f, cabs = 0.f;
    if (r < VOCABN) {
        const float4* vr = (const float4*)(V + (size_t)r * 64);
        float ss = 0.f;
        #pragma unroll
        for (int j = 0; j < 16; j++) {
            float4 v = vr[j];
            ss += v.x*v.x + v.y*v.y + v.z*v.z + v.w*v.w;
            vmax = fmaxf(vmax, fmaxf(fmaxf(fabsf(v.x), fabsf(v.y)),
                                     fmaxf(fabsf(v.z), fabsf(v.w))));
        }
        cabs = fabsf(bias[r] - 0.5f * ss);
    }
    #pragma unroll
    for (int off = 16; off > 0; off >>= 1) {
        vmax = fmaxf(vmax, __shfl_xor_sync(0xFFFFFFFFu, vmax, off));
        cabs = fmaxf(cabs, __shfl_xor_sync(0xFFFFFFFFu, cabs, off));
    }
    if (lane == 0) {
        atomicMax(&sm2[0], __float_as_int(vmax));
        atomicMax(&sm2[1], __float_as_int(cabs));
    }
    __syncthreads();
    if (tid < 2) atomicMax(&g_maxb[tid], sm2[tid]);
}

__device__ __forceinline__ void quant2(float v, float s, signed char& h8, signed char& l8) {
    float q = v * s;
    float h = rintf(q);
    float l = rintf((q - h) * 256.f);
    if (l > 127.f) l = 127.f;
    h8 = (signed char)(int)h;
    l8 = (signed char)(int)l;
}

// ---------------- pass 2: quantize V cols + c; conflict-free transposed smem ----------------
__global__ void fm_prep(const float* __restrict__ V, const float* __restrict__ bias) {
    __shared__ float smT[64][68];
    int i0 = blockIdx.x * 64;
    int tid = threadIdx.x;

    float mV = __int_as_float(g_maxb[0]);
    float sV = (mV > 0.f) ? 127.f / mV : 1.f;
    float mC = __int_as_float(g_maxb[1]);
    float sC = (mC > 0.f) ? 127.f / mC : 1.f;

    #pragma unroll
    for (int pass = 0; pass < 4; pass++) {
        int idx = pass * 256 + tid;
        int i  = idx & 63;
        int f4 = (idx >> 6) * 4;
        int gi = i0 + i;
        float4 v = (gi < VOCABN)
                 ? *(const float4*)(V + (size_t)gi * 64 + f4)
                 : make_float4(0.f, 0.f, 0.f, 0.f);
        smT[f4 + 0][i] = v.x;
        smT[f4 + 1][i] = v.y;
        smT[f4 + 2][i] = v.z;
        smT[f4 + 3][i] = v.w;
    }
    __syncthreads();

    if (tid < 64) {
        float ssum = 0.f;
        #pragma unroll
        for (int f = 0; f < 64; f++) { float v = smT[f][tid]; ssum += v * v; }
        int gi = i0 + tid;
        float cv = (gi < VOCABN) ? (bias[gi] - 0.5f * ssum) : 0.f;
        signed char h8, l8;
        quant2(cv, sC, h8, l8);
        g_ch8[i0 + tid] = h8;
        g_cl8[i0 + tid] = l8;
    }

    #pragma unroll
    for (int pass = 0; pass < 4; pass++) {
        int idx = pass * 256 + tid;
        int f  = idx >> 4;
        int i4 = (idx & 15) * 4;
        float4 v = *(const float4*)&smT[f][i4];
        char4 h4, l4;
        quant2(v.x, sV, (signed char&)h4.x, (signed char&)l4.x);
        quant2(v.y, sV, (signed char&)h4.y, (signed char&)l4.y);
        quant2(v.z, sV, (signed char&)h4.z, (signed char&)l4.z);
        quant2(v.w, sV, (signed char&)h4.w, (signed char&)l4.w);
        *(char4*)&g_Bh8[(size_t)f * K_PAD + i0 + i4] = h4;
        *(char4*)&g_Bl8[(size_t)f * K_PAD + i0 + i4] = l4;
    }
}

// ---------------- main: split-K s8 GEMM + dp4a linear term; cp.async A ring (depth 4) ----------------
__global__ void __launch_bounds__(128, 2) fm_main(const int* __restrict__ x) {
    extern __shared__ __align__(16) char dsm[];
    const unsigned sbase = s2u(dsm);

    const int tid  = threadIdx.x;
    const int w    = tid >> 5;
    const int lane = tid & 31;
    const int gid  = lane >> 2;
    const int t4   = (lane & 3) * 4;
    const int t2   = (lane & 3) * 2;
    const int mt   = blockIdx.x & (M_TILES - 1);
    const int ks   = blockIdx.x >> 5;
    const int m0   = mt * 128;
    const int k0   = ks * K_PER;

    const int* xr[4];
    bool nl[4];
    #pragma unroll
    for (int j = 0; j < 4; j++) {
        int r = m0 + w * 32 + j * 8 + gid;
        xr[j] = x + (size_t)r * VOCABN;
        nl[j] = (r != BB - 1);
    }

    int accH[8][2][4], accL[8][2][4];
    #pragma unroll
    for (int n = 0; n < 8; n++)
        #pragma unroll
        for (int m = 0; m < 2; m++)
            #pragma unroll
            for (int i = 0; i < 4; i++) { accH[n][m][i] = 0; accL[n][m][i] = 0; }
    int cH[4] = {0, 0, 0, 0}, cL[4] = {0, 0, 0, 0};

    auto stageB = [&](int st, int k) {
        #pragma unroll
        for (int j = 0; j < 8; j++) {
            int c = tid + j * 128;
            int limb = (c >= 512) ? 1 : 0;
            int cc = c - limb * 512;
            int n = cc >> 3, ch = cc & 7;
            const signed char* g = limb ? g_Bl8 : g_Bh8;
            cp16(dsm + st * (2 * LIMB_B) + limb * LIMB_B + n * BROW8 + ch * 16,
                 g + (size_t)n * K_PAD + k + ch * 16);
        }
        if (tid < 16) {
            int limb = tid >> 3, ch = tid & 7;
            const signed char* g = limb ? g_cl8 : g_ch8;
            cp16(dsm + SC_OFF + st * 256 + limb * 128 + ch * 16, g + k + ch * 16);
        }
        asm volatile("cp.async.commit_group;");
    };

    // stage A batch g into ring slot g&3 (8x16B per thread, self-consumed); one commit
    auto cpA = [&](int g) {
        char* base = dsm + A_OFF + (g & 3) * A_SLOT + tid * 16;
        int cb = k0 + g * 32;
        #pragma unroll
        for (int mf = 0; mf < 2; mf++)
            #pragma unroll
            for (int q = 0; q < 4; q++) {
                int i = mf * 4 + q;
                const int* p = xr[mf * 2 + (q & 1)];
                int c = cb + (q >> 1) * 16 + t4;
                char* dst = base + i * 2048;
                if (nl[mf * 2 + (q & 1)] | (c < VOCABN)) cp16(dst, p + c);
                else *(int4*)dst = make_int4(0, 0, 0, 0);
            }
        asm volatile("cp.async.commit_group;");
    };

    unsigned pa[8];
    auto consumeA = [&](int g) {
        const char* base = dsm + A_OFF + (g & 3) * A_SLOT + tid * 16;
        #pragma unroll
        for (int i = 0; i < 8; i++) {
            int4 v = *(const int4*)(base + i * 2048);
            pa[i] = (unsigned)v.x | ((unsigned)v.y << 8)
                  | ((unsigned)v.z << 16) | ((unsigned)v.w << 24);
        }
    };

    const unsigned offX4 = (unsigned)((lane & 15) * BROW8 + (lane >> 4) * 16);

    auto doLimb = [&](unsigned lb, int (&acc)[8][2][4]) {
        #pragma unroll
        for (int j = 0; j < 4; j++) {
            unsigned bm[4];
            ldsm4(bm, lb + (unsigned)j * (16 * BROW8) + offX4);
            #pragma unroll
            for (int mf = 0; mf < 2; mf++) {
                mma_s8(acc[2 * j][mf],     pa + mf * 4, bm[0], bm[2]);
                mma_s8(acc[2 * j + 1][mf], pa + mf * 4, bm[1], bm[3]);
            }
        }
    };

    // prologue: B stage 0 + A batches 0..2; ensure B(0) arrived (A0..A2 may stay pending)
    stageB(0, k0);
    cpA(0); cpA(1); cpA(2);
    asm volatile("cp.async.wait_group 3;");

    for (int it = 0; it < ITERS; it++) {
        const int p = it & 1;
        __syncthreads();   // orders prior-iter waits (visibility) + protects stage reuse
        if (it + 1 < ITERS) stageB(p ^ 1, k0 + (it + 1) * TILE_K);

        int wc[4][4];
        #pragma unroll
        for (int s = 0; s < 4; s++) {
            wc[s][0] = *(const int*)(dsm + SC_OFF + p * 256 + s * 32 + t4);
            wc[s][1] = *(const int*)(dsm + SC_OFF + p * 256 + s * 32 + 16 + t4);
            wc[s][2] = *(const int*)(dsm + SC_OFF + p * 256 + 128 + s * 32 + t4);
            wc[s][3] = *(const int*)(dsm + SC_OFF + p * 256 + 128 + s * 32 + 16 + t4);
        }

        const unsigned stb = sbase + (unsigned)p * (2 * LIMB_B);
        #pragma unroll
        for (int s = 0; s < 4; s++) {
            const int g = it * 4 + s;
            // allows the 2 most recent groups pending -> A(g) and B(stage p) complete
            asm volatile("cp.async.wait_group 2;");
            cpA(g + 3);                         // refill slot consumed at step g-1
            consumeA(g);
            {
                cH[0] = __dp4a((int)pa[0], wc[s][0], cH[0]);
                cH[1] = __dp4a((int)pa[1], wc[s][0], cH[1]);
                cH[0] = __dp4a((int)pa[2], wc[s][1], cH[0]);
                cH[1] = __dp4a((int)pa[3], wc[s][1], cH[1]);
                cH[2] = __dp4a((int)pa[4], wc[s][0], cH[2]);
                cH[3] = __dp4a((int)pa[5], wc[s][0], cH[3]);
                cH[2] = __dp4a((int)pa[6], wc[s][1], cH[2]);
                cH[3] = __dp4a((int)pa[7], wc[s][1], cH[3]);
                cL[0] = __dp4a((int)pa[0], wc[s][2], cL[0]);
                cL[1] = __dp4a((int)pa[1], wc[s][2], cL[1]);
                cL[0] = __dp4a((int)pa[2], wc[s][3], cL[0]);
                cL[1] = __dp4a((int)pa[3], wc[s][3], cL[1]);
                cL[2] = __dp4a((int)pa[4], wc[s][2], cL[2]);
                cL[3] = __dp4a((int)pa[5], wc[s][2], cL[3]);
                cL[2] = __dp4a((int)pa[6], wc[s][3], cL[2]);
                cL[3] = __dp4a((int)pa[7], wc[s][3], cL[3]);
            }
            doLimb(stb + (unsigned)s * 32, accH);
            doLimb(stb + LIMB_B + (unsigned)s * 32, accL);
        }
    }

    // ---- epilogue: dequant + split-K accumulate ----
    float mV = __int_as_float(g_maxb[0]);
    float mC = __int_as_float(g_maxb[1]);
    const double invV = (mV > 0.f) ? (double)mV / 32512.0 : (1.0 / 256.0);
    const double invC = (mC > 0.f) ? (double)mC / 32512.0 : (1.0 / 256.0);

    #pragma unroll
    for (int mf = 0; mf < 2; mf++) {
        int rowA = m0 + w * 32 + mf * 16 + gid;
        #pragma unroll
        for (int nf = 0; nf < 8; nf++) {
            #pragma unroll
            for (int cc = 0; cc < 2; cc++) {
                int n = nf * 8 + t2 + cc;
                float v0 = (float)((double)(256LL * accH[nf][mf][cc]     + accL[nf][mf][cc])     * invV);
                float v1 = (float)((double)(256LL * accH[nf][mf][2 + cc] + accL[nf][mf][2 + cc]) * invV);
                atomicAdd(&g_xv[(size_t)rowA * FF + n],       v0);
                atomicAdd(&g_xv[(size_t)(rowA + 8) * FF + n], v1);
            }
        }
    }
    #pragma unroll
    for (int j = 0; j < 4; j++) {
        int h = cH[j], l = cL[j];
        h += __shfl_xor_sync(0xFFFFFFFFu, h, 1);
        h += __shfl_xor_sync(0xFFFFFFFFu, h, 2);
        l += __shfl_xor_sync(0xFFFFFFFFu, l, 1);
        l += __shfl_xor_sync(0xFFFFFFFFu, l, 2);
        if ((lane & 3) == 0) {
            int row = m0 + w * 32 + j * 8 + gid;
            atomicAdd(&g_xc[row],
                      (float)((double)(256LL * h + l) * invC));
        }
    }
}

// ---------------- finalize: out = g + xc + 0.5||xv||^2; re-zero scratch ----------------
__global__ void fm_fin(const float* __restrict__ gb, float* __restrict__ out) {
    int t = blockIdx.x * blockDim.x + threadIdx.x;
    int b = t >> 2, part = t & 3;
    float4* v = (float4*)&g_xv[(size_t)b * FF + part * 16];
    float ss = 0.f;
    #pragma unroll
    for (int i = 0; i < 4; i++) {
        float4 q = v[i];
        ss += q.x * q.x + q.y * q.y + q.z * q.z + q.w * q.w;
        v[i] = make_float4(0.f, 0.f, 0.f, 0.f);
    }
    ss += __shfl_xor_sync(0xFFFFFFFFu, ss, 1);
    ss += __shfl_xor_sync(0xFFFFFFFFu, ss, 2);
    if (part == 0) {
        out[b] = gb[0] + g_xc[b] + 0.5f * ss;
        g_xc[b] = 0.f;
    }
    if (t < 2) g_maxb[t] = 0;
}

extern "C" void kernel_launch(void* const* d_in, const int* in_sizes, int n_in,
                              void* d_out, int out_size) {
    const int*   x    = (const int*)d_in[0];
    const float* V    = (const float*)d_in[1];
    const float* bias = (const float*)d_in[2];
    const float* gb   = (const float*)d_in[3];
    float* out = (float*)d_out;
    (void)in_sizes; (void)n_in; (void)out_size;

    cudaFuncSetAttribute(fm_main, cudaFuncAttributeMaxDynamicSharedMemorySize, SMEM_MAIN);

    fm_scale1<<<196, 256>>>(V, bias);
    fm_prep<<<K_PAD / 64, 256>>>(V, bias);
    fm_main<<<M_TILES * K_SPLITS, 128, SMEM_MAIN>>>(x);
    fm_fin<<<64, 256>>>(gb, out);
}

// round 16
// speedup vs baseline: 1.5802x; 1.0117x over previous
#include <cuda_runtime.h>

#define BB       4096
#define VOCABN   50000
#define FF       64
#define K_PAD    50688       // 9 * 5632 = 792 * 64, B zero-padded beyond 50000
#define K_SPLITS 9
#define K_PER    5632        // 44 * 128
#define ITERS    44
#define TILE_K   128
#define M_TILES  32
#define NB       64          // V cols only; c handled via dp4a
#define BROW8    144         // int8 smem row stride (128 data + 16 pad)
#define LIMB_B   (NB * BROW8)   // 9216 bytes per limb per stage

// ---- device-global scratch (zero-initialized at load; invariant restored by fm_fin) ----
__device__ __align__(16) signed char g_Bh8[NB * K_PAD];
__device__ __align__(16) signed char g_Bl8[NB * K_PAD];
__device__ __align__(16) signed char g_ch8[K_PAD];
__device__ __align__(16) signed char g_cl8[K_PAD];
__device__ float g_xv[BB * FF];
__device__ float g_xc[BB];
__device__ int   g_maxb[2];      // [0] = max|V|, [1] = max|c|

__device__ __forceinline__ unsigned s2u(const void* p) {
    return (unsigned)__cvta_generic_to_shared(p);
}
__device__ __forceinline__ void cp16(void* dst, const void* src) {
    asm volatile("cp.async.cg.shared.global [%0], [%1], 16;"
                 :: "r"(s2u(dst)), "l"(src));
}
__device__ __forceinline__ void ldsm4(unsigned* r, unsigned addr) {
    asm volatile("ldmatrix.sync.aligned.m8n8.x4.shared.b16 {%0,%1,%2,%3}, [%4];"
                 : "=r"(r[0]), "=r"(r[1]), "=r"(r[2]), "=r"(r[3]) : "r"(addr));
}
__device__ __forceinline__ void mma_s8(int* d, const unsigned* a, unsigned b0, unsigned b1) {
    asm volatile(
        "mma.sync.aligned.m16n8k32.row.col.s32.s8.s8.s32 "
        "{%0,%1,%2,%3}, {%4,%5,%6,%7}, {%8,%9}, {%0,%1,%2,%3};"
        : "+r"(d[0]), "+r"(d[1]), "+r"(d[2]), "+r"(d[3])
        : "r"(a[0]), "r"(a[1]), "r"(a[2]), "r"(a[3]), "r"(b0), "r"(b1));
}

// ---------------- pass 1: global max|V| and max|c| ----------------
__global__ void fm_scale1(const float* __restrict__ V, const float* __restrict__ bias) {
    __shared__ int sm2[2];
    int tid = threadIdx.x, lane = tid & 31;
    if (tid < 2) sm2[tid] = 0;
    __syncthreads();
    int r = blockIdx.x * 256 + tid;
    float vmax = 0.f, cabs = 0.f;
    if (r < VOCABN) {
        const float4* vr = (const float4*)(V + (size_t)r * 64);
        float ss = 0.f;
        #pragma unroll
        for (int j = 0; j < 16; j++) {
            float4 v = vr[j];
            ss += v.x*v.x + v.y*v.y + v.z*v.z + v.w*v.w;
            vmax = fmaxf(vmax, fmaxf(fmaxf(fabsf(v.x), fabsf(v.y)),
                                     fmaxf(fabsf(v.z), fabsf(v.w))));
        }
        cabs = fabsf(bias[r] - 0.5f * ss);
    }
    #pragma unroll
    for (int off = 16; off > 0; off >>= 1) {
        vmax = fmaxf(vmax, __shfl_xor_sync(0xFFFFFFFFu, vmax, off));
        cabs = fmaxf(cabs, __shfl_xor_sync(0xFFFFFFFFu, cabs, off));
    }
    if (lane == 0) {
        atomicMax(&sm2[0], __float_as_int(vmax));
        atomicMax(&sm2[1], __float_as_int(cabs));
    }
    __syncthreads();
    if (tid < 2) atomicMax(&g_maxb[tid], sm2[tid]);
}

__device__ __forceinline__ void quant2(float v, float s, signed char& h8, signed char& l8) {
    float q = v * s;
    float h = rintf(q);
    float l = rintf((q - h) * 256.f);
    if (l > 127.f) l = 127.f;
    h8 = (signed char)(int)h;
    l8 = (signed char)(int)l;
}

// ---------------- pass 2: quantize V cols + c; conflict-free transposed smem ----------------
__global__ void fm_prep(const float* __restrict__ V, const float* __restrict__ bias) {
    __shared__ float smT[64][68];
    int i0 = blockIdx.x * 64;
    int tid = threadIdx.x;

    float mV = __int_as_float(g_maxb[0]);
    float sV = (mV > 0.f) ? 127.f / mV : 1.f;
    float mC = __int_as_float(g_maxb[1]);
    float sC = (mC > 0.f) ? 127.f / mC : 1.f;

    #pragma unroll
    for (int pass = 0; pass < 4; pass++) {
        int idx = pass * 256 + tid;
        int i  = idx & 63;
        int f4 = (idx >> 6) * 4;
        int gi = i0 + i;
        float4 v = (gi < VOCABN)
                 ? *(const float4*)(V + (size_t)gi * 64 + f4)
                 : make_float4(0.f, 0.f, 0.f, 0.f);
        smT[f4 + 0][i] = v.x;
        smT[f4 + 1][i] = v.y;
        smT[f4 + 2][i] = v.z;
        smT[f4 + 3][i] = v.w;
    }
    __syncthreads();

    if (tid < 64) {
        float ssum = 0.f;
        #pragma unroll
        for (int f = 0; f < 64; f++) { float v = smT[f][tid]; ssum += v * v; }
        int gi = i0 + tid;
        float cv = (gi < VOCABN) ? (bias[gi] - 0.5f * ssum) : 0.f;
        signed char h8, l8;
        quant2(cv, sC, h8, l8);
        g_ch8[i0 + tid] = h8;
        g_cl8[i0 + tid] = l8;
    }

    #pragma unroll
    for (int pass = 0; pass < 4; pass++) {
        int idx = pass * 256 + tid;
        int f  = idx >> 4;
        int i4 = (idx & 15) * 4;
        float4 v = *(const float4*)&smT[f][i4];
        char4 h4, l4;
        quant2(v.x, sV, (signed char&)h4.x, (signed char&)l4.x);
        quant2(v.y, sV, (signed char&)h4.y, (signed char&)l4.y);
        quant2(v.z, sV, (signed char&)h4.z, (signed char&)l4.z);
        quant2(v.w, sV, (signed char&)h4.w, (signed char&)l4.w);
        *(char4*)&g_Bh8[(size_t)f * K_PAD + i0 + i4] = h4;
        *(char4*)&g_Bl8[(size_t)f * K_PAD + i0 + i4] = l4;
    }
}

// ---------------- main: 256 threads, m16 warps, reg depth-2 A, s8 GEMM + dp4a c ----------------
__global__ void __launch_bounds__(256, 2) fm_main(const int* __restrict__ x) {
    __shared__ __align__(16) signed char sB[2][2][NB][BROW8];   // 36.9KB
    __shared__ __align__(16) signed char sC[2][2][128];          // 512B

    const int tid  = threadIdx.x;
    const int w    = tid >> 5;           // 0..7, each warp = m16 tile
    const int lane = tid & 31;
    const int gid  = lane >> 2;
    const int t4   = (lane & 3) * 4;
    const int t2   = (lane & 3) * 2;
    const int mt   = blockIdx.x & (M_TILES - 1);
    const int ks   = blockIdx.x >> 5;
    const int m0   = mt * 128;
    const int k0   = ks * K_PER;

    const int r0 = m0 + w * 16 + gid;
    const int* xr0 = x + (size_t)r0 * VOCABN;
    const int* xr1 = xr0 + (size_t)8 * VOCABN;
    const bool nl0 = (r0 != BB - 1);
    const bool nl1 = (r0 + 8 != BB - 1);

    int accH[8][4], accL[8][4];
    #pragma unroll
    for (int n = 0; n < 8; n++)
        #pragma unroll
        for (int i = 0; i < 4; i++) { accH[n][i] = 0; accL[n][i] = 0; }
    int cH[2] = {0, 0}, cL[2] = {0, 0};

    auto stageB = [&](int st, int k) {
        #pragma unroll
        for (int j = 0; j < 4; j++) {
            int c = tid + j * 256;
            int limb = (c >= 512) ? 1 : 0;
            int cc = c - limb * 512;
            int n = cc >> 3, ch = cc & 7;
            const signed char* g = limb ? g_Bl8 : g_Bh8;
            cp16(&sB[st][limb][n][ch * 16], g + (size_t)n * K_PAD + k + ch * 16);
        }
        if (tid < 16) {
            int limb = tid >> 3, ch = tid & 7;
            const signed char* g = limb ? g_cl8 : g_ch8;
            cp16(&sC[st][limb][ch * 16], g + k + ch * 16);
        }
        asm volatile("cp.async.commit_group;");
    };

    int4 raw[2][4];
    unsigned pa[4];
    auto loadA = [&](int pb, int cb) {
        #pragma unroll
        for (int q = 0; q < 4; q++) {
            const int* p = (q & 1) ? xr1 : xr0;
            int c = cb + (q >> 1) * 16 + t4;
            bool ok = ((q & 1) ? nl1 : nl0) | (c < VOCABN);
            raw[pb][q] = ok ? *(const int4*)(p + c) : make_int4(0, 0, 0, 0);
        }
    };
    auto packA = [&](int pb) {
        #pragma unroll
        for (int i = 0; i < 4; i++) {
            int4 v = raw[pb][i];
            pa[i] = (unsigned)v.x | ((unsigned)v.y << 8)
                  | ((unsigned)v.z << 16) | ((unsigned)v.w << 24);
        }
    };

    const unsigned offX4 = (unsigned)((lane & 15) * BROW8 + (lane >> 4) * 16);
    const unsigned sb0 = s2u(&sB[0][0][0][0]);

    auto doLimb = [&](unsigned lb, int (&acc)[8][4]) {
        #pragma unroll
        for (int j = 0; j < 4; j++) {
            unsigned bm[4];
            ldsm4(bm, lb + (unsigned)j * (16 * BROW8) + offX4);
            mma_s8(acc[2 * j],     pa, bm[0], bm[2]);
            mma_s8(acc[2 * j + 1], pa, bm[1], bm[3]);
        }
    };

    stageB(0, k0);
    loadA(0, k0);           // g = 0
    loadA(1, k0 + 32);      // g = 1
    asm volatile("cp.async.wait_group 0;");   // B(0) complete (per-thread)

    for (int it = 0; it < ITERS; it++) {
        const int p = it & 1;
        __syncthreads();    // publish B(p); protect stage p^1 reuse
        if (it + 1 < ITERS) stageB(p ^ 1, k0 + (it + 1) * TILE_K);

        const unsigned stb = sb0 + (unsigned)p * (2 * LIMB_B);
        #pragma unroll
        for (int s = 0; s < 4; s++) {
            const int g = it * 4 + s;
            const int pb = g & 1;
            packA(pb);                          // consume batch loaded at g-2
            loadA(pb, k0 + (g + 2) * 32);       // issue batch for g+2
            {
                int w0h = *(const int*)&sC[p][0][s * 32 + t4];
                int w1h = *(const int*)&sC[p][0][s * 32 + 16 + t4];
                int w0l = *(const int*)&sC[p][1][s * 32 + t4];
                int w1l = *(const int*)&sC[p][1][s * 32 + 16 + t4];
                cH[0] = __dp4a((int)pa[0], w0h, cH[0]);
                cH[1] = __dp4a((int)pa[1], w0h, cH[1]);
                cH[0] = __dp4a((int)pa[2], w1h, cH[0]);
                cH[1] = __dp4a((int)pa[3], w1h, cH[1]);
                cL[0] = __dp4a((int)pa[0], w0l, cL[0]);
                cL[1] = __dp4a((int)pa[1], w0l, cL[1]);
                cL[0] = __dp4a((int)pa[2], w1l, cL[0]);
                cL[1] = __dp4a((int)pa[3], w1l, cL[1]);
            }
            doLimb(stb + (unsigned)s * 32, accH);
            doLimb(stb + LIMB_B + (unsigned)s * 32, accL);
        }
        asm volatile("cp.async.wait_group 0;");  // B(p^1) complete before next iter's sync
    }

    // ---- epilogue: dequant + split-K accumulate ----
    float mV = __int_as_float(g_maxb[0]);
    float mC = __int_as_float(g_maxb[1]);
    const double invV = (mV > 0.f) ? (double)mV / 32512.0 : (1.0 / 256.0);
    const double invC = (mC > 0.f) ? (double)mC / 32512.0 : (1.0 / 256.0);

    #pragma unroll
    for (int nf = 0; nf < 8; nf++) {
        #pragma unroll
        for (int cc = 0; cc < 2; cc++) {
            int n = nf * 8 + t2 + cc;
            float v0 = (float)((double)(256LL * accH[nf][cc]     + accL[nf][cc])     * invV);
            float v1 = (float)((double)(256LL * accH[nf][2 + cc] + accL[nf][2 + cc]) * invV);
            atomicAdd(&g_xv[(size_t)r0 * FF + n],       v0);
            atomicAdd(&g_xv[(size_t)(r0 + 8) * FF + n], v1);
        }
    }
    #pragma unroll
    for (int j = 0; j < 2; j++) {
        int h = cH[j], l = cL[j];
        h += __shfl_xor_sync(0xFFFFFFFFu, h, 1);
        h += __shfl_xor_sync(0xFFFFFFFFu, h, 2);
        l += __shfl_xor_sync(0xFFFFFFFFu, l, 1);
        l += __shfl_xor_sync(0xFFFFFFFFu, l, 2);
        if ((lane & 3) == 0) {
            atomicAdd(&g_xc[r0 + j * 8],
                      (float)((double)(256LL * h + l) * invC));
        }
    }
}

// ---------------- finalize: out = g + xc + 0.5||xv||^2; re-zero scratch ----------------
__global__ void fm_fin(const float* __restrict__ gb, float* __restrict__ out) {
    int t = blockIdx.x * blockDim.x + threadIdx.x;
    int b = t >> 2, part = t & 3;
    float4* v = (float4*)&g_xv[(size_t)b * FF + part * 16];
    float ss = 0.f;
    #pragma unroll
    for (int i = 0; i < 4; i++) {
        float4 q = v[i];
        ss += q.x * q.x + q.y * q.y + q.z * q.z + q.w * q.w;
        v[i] = make_float4(0.f, 0.f, 0.f, 0.f);
    }
    ss += __shfl_xor_sync(0xFFFFFFFFu, ss, 1);
    ss += __shfl_xor_sync(0xFFFFFFFFu, ss, 2);
    if (part == 0) {
        out[b] = gb[0] + g_xc[b] + 0.5f * ss;
        g_xc[b] = 0.f;
    }
    if (t < 2) g_maxb[t] = 0;
}

extern "C" void kernel_launch(void* const* d_in, const int* in_sizes, int n_in,
                              void* d_out, int out_size) {
    const int*   x    = (const int*)d_in[0];
    const float* V    = (const float*)d_in[1];
    const float* bias = (const float*)d_in[2];
    const float* gb   = (const float*)d_in[3];
    float* out = (float*)d_out;
    (void)in_sizes; (void)n_in; (void)out_size;

    fm_scale1<<<196, 256>>>(V, bias);
    fm_prep<<<K_PAD / 64, 256>>>(V, bias);
    fm_main<<<M_TILES * K_SPLITS, 256>>>(x);
    fm_fin<<<64, 256>>>(gb, out);
}

// round 17
// speedup vs baseline: 1.5940x; 1.0087x over previous
#include <cuda_runtime.h>

#define BB       4096
#define VOCABN   50000
#define FF       64
#define K_PAD    50688       // 9 * 5632 = 792 * 64, B zero-padded beyond 50000
#define K_SPLITS 9
#define K_PER    5632        // 44 * 128
#define ITERS    44
#define TILE_K   128
#define M_TILES  32
#define NB       64          // V cols only; c handled via dp4a
#define BROW8    144         // int8 smem row stride (128 data + 16 pad)
#define LIMB_B   (NB * BROW8)   // 9216 bytes per limb per stage
#define PREP_BLK 792            // fused prep grid (co-resident: <= 148*8)

// ---- device-global scratch (zero-initialized at load; invariant restored by fm_fin) ----
__device__ __align__(16) signed char g_Bh8[NB * K_PAD];
__device__ __align__(16) signed char g_Bl8[NB * K_PAD];
__device__ __align__(16) signed char g_ch8[K_PAD];
__device__ __align__(16) signed char g_cl8[K_PAD];
__device__ float g_xv[BB * FF];
__device__ float g_xc[BB];
__device__ int   g_maxb[2];      // [0] = max|V|, [1] = max|c|
__device__ int   g_cnt;          // spin-barrier counter (reset by fm_fin)

__device__ __forceinline__ unsigned s2u(const void* p) {
    return (unsigned)__cvta_generic_to_shared(p);
}
__device__ __forceinline__ void cp16(void* dst, const void* src) {
    asm volatile("cp.async.cg.shared.global [%0], [%1], 16;"
                 :: "r"(s2u(dst)), "l"(src));
}
__device__ __forceinline__ void ldsm4(unsigned* r, unsigned addr) {
    asm volatile("ldmatrix.sync.aligned.m8n8.x4.shared.b16 {%0,%1,%2,%3}, [%4];"
                 : "=r"(r[0]), "=r"(r[1]), "=r"(r[2]), "=r"(r[3]) : "r"(addr));
}
__device__ __forceinline__ void mma_s8(int* d, const unsigned* a, unsigned b0, unsigned b1) {
    asm volatile(
        "mma.sync.aligned.m16n8k32.row.col.s32.s8.s8.s32 "
        "{%0,%1,%2,%3}, {%4,%5,%6,%7}, {%8,%9}, {%0,%1,%2,%3};"
        : "+r"(d[0]), "+r"(d[1]), "+r"(d[2]), "+r"(d[3])
        : "r"(a[0]), "r"(a[1]), "r"(a[2]), "r"(a[3]), "r"(b0), "r"(b1));
}

__device__ __forceinline__ void quant2(float v, float s, signed char& h8, signed char& l8) {
    float q = v * s;
    float h = rintf(q);
    float l = rintf((q - h) * 256.f);
    if (l > 127.f) l = 127.f;
    h8 = (signed char)(int)h;
    l8 = (signed char)(int)l;
}

// ---------------- fused: per-chunk max -> device spin barrier -> quantize ----------------
__global__ void __launch_bounds__(256, 8) fm_prep(const float* __restrict__ V,
                                                  const float* __restrict__ bias) {
    __shared__ float smT[64][68];     // [f][i], transposed chunk
    __shared__ float csv[64];         // c values per row
    __shared__ int sm2[2];
    int i0 = blockIdx.x * 64;
    int tid = threadIdx.x, lane = tid & 31;
    if (tid < 2) sm2[tid] = 0;

    // phase 1: load chunk transposed; track per-thread max|V|
    float vmax = 0.f;
    #pragma unroll
    for (int pass = 0; pass < 4; pass++) {
        int idx = pass * 256 + tid;
        int i  = idx & 63;
        int f4 = (idx >> 6) * 4;
        int gi = i0 + i;
        float4 v = (gi < VOCABN)
                 ? *(const float4*)(V + (size_t)gi * 64 + f4)
                 : make_float4(0.f, 0.f, 0.f, 0.f);
        smT[f4 + 0][i] = v.x;
        smT[f4 + 1][i] = v.y;
        smT[f4 + 2][i] = v.z;
        smT[f4 + 3][i] = v.w;
        vmax = fmaxf(vmax, fmaxf(fmaxf(fabsf(v.x), fabsf(v.y)),
                                 fmaxf(fabsf(v.z), fabsf(v.w))));
    }
    #pragma unroll
    for (int off = 16; off > 0; off >>= 1)
        vmax = fmaxf(vmax, __shfl_xor_sync(0xFFFFFFFFu, vmax, off));
    if (lane == 0) atomicMax(&sm2[0], __float_as_int(vmax));
    __syncthreads();

    // phase 2: c values + max|c|
    float cabs = 0.f;
    if (tid < 64) {
        float ssum = 0.f;
        #pragma unroll
        for (int f = 0; f < 64; f++) { float v = smT[f][tid]; ssum += v * v; }
        int gi = i0 + tid;
        float cv = (gi < VOCABN) ? (bias[gi] - 0.5f * ssum) : 0.f;
        csv[tid] = cv;
        cabs = fabsf(cv);
    }
    #pragma unroll
    for (int off = 16; off > 0; off >>= 1)
        cabs = fmaxf(cabs, __shfl_xor_sync(0xFFFFFFFFu, cabs, off));
    if (tid < 64 && lane == 0) atomicMax(&sm2[1], __float_as_int(cabs));
    __syncthreads();

    // publish partial maxes + spin until all blocks contributed
    if (tid == 0) {
        atomicMax(&g_maxb[0], sm2[0]);
        atomicMax(&g_maxb[1], sm2[1]);
        __threadfence();
        atomicAdd(&g_cnt, 1);
        volatile int* cnt = &g_cnt;
        while (*cnt < PREP_BLK) { }
        __threadfence();
    }
    __syncthreads();

    volatile int* vm = g_maxb;
    float mV = __int_as_float(vm[0]);
    float sV = (mV > 0.f) ? 127.f / mV : 1.f;
    float mC = __int_as_float(vm[1]);
    float sC = (mC > 0.f) ? 127.f / mC : 1.f;

    // phase 3: quantize c + V (LDS.128 reads, char4 stores)
    if (tid < 64) {
        signed char h8, l8;
        quant2(csv[tid], sC, h8, l8);
        g_ch8[i0 + tid] = h8;
        g_cl8[i0 + tid] = l8;
    }
    #pragma unroll
    for (int pass = 0; pass < 4; pass++) {
        int idx = pass * 256 + tid;
        int f  = idx >> 4;
        int i4 = (idx & 15) * 4;
        float4 v = *(const float4*)&smT[f][i4];
        char4 h4, l4;
        quant2(v.x, sV, (signed char&)h4.x, (signed char&)l4.x);
        quant2(v.y, sV, (signed char&)h4.y, (signed char&)l4.y);
        quant2(v.z, sV, (signed char&)h4.z, (signed char&)l4.z);
        quant2(v.w, sV, (signed char&)h4.w, (signed char&)l4.w);
        *(char4*)&g_Bh8[(size_t)f * K_PAD + i0 + i4] = h4;
        *(char4*)&g_Bl8[(size_t)f * K_PAD + i0 + i4] = l4;
    }
}

// ---------------- main: 256 threads, m16 warps, reg depth-2 A, s8 GEMM + dp4a c ----------------
__global__ void __launch_bounds__(256, 2) fm_main(const int* __restrict__ x) {
    __shared__ __align__(16) signed char sB[2][2][NB][BROW8];   // 36.9KB
    __shared__ __align__(16) signed char sC[2][2][128];          // 512B

    const int tid  = threadIdx.x;
    const int w    = tid >> 5;           // 0..7, each warp = m16 tile
    const int lane = tid & 31;
    const int gid  = lane >> 2;
    const int t4   = (lane & 3) * 4;
    const int t2   = (lane & 3) * 2;
    const int mt   = blockIdx.x & (M_TILES - 1);
    const int ks   = blockIdx.x >> 5;
    const int m0   = mt * 128;
    const int k0   = ks * K_PER;

    const int r0 = m0 + w * 16 + gid;
    const int* xr0 = x + (size_t)r0 * VOCABN;
    const int* xr1 = xr0 + (size_t)8 * VOCABN;
    const bool nl0 = (r0 != BB - 1);
    const bool nl1 = (r0 + 8 != BB - 1);

    int accH[8][4], accL[8][4];
    #pragma unroll
    for (int n = 0; n < 8; n++)
        #pragma unroll
        for (int i = 0; i < 4; i++) { accH[n][i] = 0; accL[n][i] = 0; }
    int cH[2] = {0, 0}, cL[2] = {0, 0};

    auto stageB = [&](int st, int k) {
        #pragma unroll
        for (int j = 0; j < 4; j++) {
            int c = tid + j * 256;
            int limb = (c >= 512) ? 1 : 0;
            int cc = c - limb * 512;
            int n = cc >> 3, ch = cc & 7;
            const signed char* g = limb ? g_Bl8 : g_Bh8;
            cp16(&sB[st][limb][n][ch * 16], g + (size_t)n * K_PAD + k + ch * 16);
        }
        if (tid < 16) {
            int limb = tid >> 3, ch = tid & 7;
            const signed char* g = limb ? g_cl8 : g_ch8;
            cp16(&sC[st][limb][ch * 16], g + k + ch * 16);
        }
        asm volatile("cp.async.commit_group;");
    };

    int4 raw[2][4];
    unsigned pa[4];
    auto loadA = [&](int pb, int cb) {
        #pragma unroll
        for (int q = 0; q < 4; q++) {
            const int* p = (q & 1) ? xr1 : xr0;
            int c = cb + (q >> 1) * 16 + t4;
            bool ok = ((q & 1) ? nl1 : nl0) | (c < VOCABN);
            raw[pb][q] = ok ? *(const int4*)(p + c) : make_int4(0, 0, 0, 0);
        }
    };
    auto packA = [&](int pb) {
        #pragma unroll
        for (int i = 0; i < 4; i++) {
            int4 v = raw[pb][i];
            pa[i] = (unsigned)v.x | ((unsigned)v.y << 8)
                  | ((unsigned)v.z << 16) | ((unsigned)v.w << 24);
        }
    };

    const unsigned offX4 = (unsigned)((lane & 15) * BROW8 + (lane >> 4) * 16);
    const unsigned sb0 = s2u(&sB[0][0][0][0]);

    auto doLimb = [&](unsigned lb, int (&acc)[8][4]) {
        #pragma unroll
        for (int j = 0; j < 4; j++) {
            unsigned bm[4];
            ldsm4(bm, lb + (unsigned)j * (16 * BROW8) + offX4);
            mma_s8(acc[2 * j],     pa, bm[0], bm[2]);
            mma_s8(acc[2 * j + 1], pa, bm[1], bm[3]);
        }
    };

    stageB(0, k0);
    loadA(0, k0);           // g = 0
    loadA(1, k0 + 32);      // g = 1
    asm volatile("cp.async.wait_group 0;");   // B(0) complete (per-thread)

    for (int it = 0; it < ITERS; it++) {
        const int p = it & 1;
        __syncthreads();    // publish B(p); protect stage p^1 reuse
        if (it + 1 < ITERS) stageB(p ^ 1, k0 + (it + 1) * TILE_K);

        const unsigned stb = sb0 + (unsigned)p * (2 * LIMB_B);
        #pragma unroll
        for (int s = 0; s < 4; s++) {
            const int g = it * 4 + s;
            const int pb = g & 1;
            packA(pb);                          // consume batch loaded at g-2
            loadA(pb, k0 + (g + 2) * 32);       // issue batch for g+2
            {
                int w0h = *(const int*)&sC[p][0][s * 32 + t4];
                int w1h = *(const int*)&sC[p][0][s * 32 + 16 + t4];
                int w0l = *(const int*)&sC[p][1][s * 32 + t4];
                int w1l = *(const int*)&sC[p][1][s * 32 + 16 + t4];
                cH[0] = __dp4a((int)pa[0], w0h, cH[0]);
                cH[1] = __dp4a((int)pa[1], w0h, cH[1]);
                cH[0] = __dp4a((int)pa[2], w1h, cH[0]);
                cH[1] = __dp4a((int)pa[3], w1h, cH[1]);
                cL[0] = __dp4a((int)pa[0], w0l, cL[0]);
                cL[1] = __dp4a((int)pa[1], w0l, cL[1]);
                cL[0] = __dp4a((int)pa[2], w1l, cL[0]);
                cL[1] = __dp4a((int)pa[3], w1l, cL[1]);
            }
            doLimb(stb + (unsigned)s * 32, accH);
            doLimb(stb + LIMB_B + (unsigned)s * 32, accL);
        }
        asm volatile("cp.async.wait_group 0;");  // B(p^1) complete before next iter's sync
    }

    // ---- epilogue: dequant + split-K accumulate ----
    float mV = __int_as_float(g_maxb[0]);
    float mC = __int_as_float(g_maxb[1]);
    const double invV = (mV > 0.f) ? (double)mV / 32512.0 : (1.0 / 256.0);
    const double invC = (mC > 0.f) ? (double)mC / 32512.0 : (1.0 / 256.0);

    #pragma unroll
    for (int nf = 0; nf < 8; nf++) {
        #pragma unroll
        for (int cc = 0; cc < 2; cc++) {
            int n = nf * 8 + t2 + cc;
            float v0 = (float)((double)(256LL * accH[nf][cc]     + accL[nf][cc])     * invV);
            float v1 = (float)((double)(256LL * accH[nf][2 + cc] + accL[nf][2 + cc]) * invV);
            atomicAdd(&g_xv[(size_t)r0 * FF + n],       v0);
            atomicAdd(&g_xv[(size_t)(r0 + 8) * FF + n], v1);
        }
    }
    #pragma unroll
    for (int j = 0; j < 2; j++) {
        int h = cH[j], l = cL[j];
        h += __shfl_xor_sync(0xFFFFFFFFu, h, 1);
        h += __shfl_xor_sync(0xFFFFFFFFu, h, 2);
        l += __shfl_xor_sync(0xFFFFFFFFu, l, 1);
        l += __shfl_xor_sync(0xFFFFFFFFu, l, 2);
        if ((lane & 3) == 0) {
            atomicAdd(&g_xc[r0 + j * 8],
                      (float)((double)(256LL * h + l) * invC));
        }
    }
}

// ---------------- finalize: out = g + xc + 0.5||xv||^2; re-zero scratch ----------------
__global__ void fm_fin(const float* __restrict__ gb, float* __restrict__ out) {
    int t = blockIdx.x * blockDim.x + threadIdx.x;   // 128 blocks * 128 threads
    int b = t >> 2, part = t & 3;
    float4* v = (float4*)&g_xv[(size_t)b * FF + part * 16];
    float ss = 0.f;
    #pragma unroll
    for (int i = 0; i < 4; i++) {
        float4 q = v[i];
        ss += q.x * q.x + q.y * q.y + q.z * q.z + q.w * q.w;
        v[i] = make_float4(0.f, 0.f, 0.f, 0.f);
    }
    ss += __shfl_xor_sync(0xFFFFFFFFu, ss, 1);
    ss += __shfl_xor_sync(0xFFFFFFFFu, ss, 2);
    if (part == 0) {
        out[b] = gb[0] + g_xc[b] + 0.5f * ss;
        g_xc[b] = 0.f;
    }
    if (t < 2) g_maxb[t] = 0;
    if (t == 2) g_cnt = 0;
}

extern "C" void kernel_launch(void* const* d_in, const int* in_sizes, int n_in,
                              void* d_out, int out_size) {
    const int*   x    = (const int*)d_in[0];
    const float* V    = (const float*)d_in[1];
    const float* bias = (const float*)d_in[2];
    const float* gb   = (const float*)d_in[3];
    float* out = (float*)d_out;
    (void)in_sizes; (void)n_in; (void)out_size;

    fm_prep<<<PREP_BLK, 256>>>(V, bias);
    fm_main<<<M_TILES * K_SPLITS, 256>>>(x);
    fm_fin<<<128, 128>>>(gb, out);
}